// round 3
// baseline (speedup 1.0000x reference)
#include <cuda_runtime.h>
#include <cstdint>

#define NMAXI 8
#define PRE   2000
#define POST  1000
#define CAP   2048
#define WORDS 32
#define TIECAP 1024
#define BANDCAP 65536

#define IMGSZ 800.0f
#define IOUTHR 0.7f
#define MINSZ 1e-3f
#define BBOXCLIP 4.135166556742356f   // log(1000/16)

#define SCANB 96   // blocks per image for full scans

// ------------------------- device scratch (static) -------------------------
__device__ unsigned int       d_hist[NMAXI][256];
__device__ unsigned int       d_prefix[NMAXI];
__device__ int                d_rankr[NMAXI];
__device__ int                d_bandCnt[NMAXI];
__device__ int                d_done[NMAXI];
__device__ unsigned long long d_band[NMAXI][BANDCAP];
__device__ unsigned long long d_mask[NMAXI][CAP][WORDS];   // 4 MB

__device__ __forceinline__ unsigned key_of(float f) {
    unsigned u = __float_as_uint(f);
    return (u & 0x80000000u) ? ~u : (u | 0x80000000u);
}

// ---------------------------------------------------------------------------
// 1) prep: zero mask + hist + counters
// ---------------------------------------------------------------------------
__global__ void k_prep() {
    size_t t = blockIdx.x * (size_t)blockDim.x + threadIdx.x;
    size_t stride = (size_t)gridDim.x * blockDim.x;
    unsigned long long* m = &d_mask[0][0][0];
    for (size_t i = t; i < (size_t)NMAXI * CAP * WORDS; i += stride) m[i] = 0ull;
    unsigned* h = &d_hist[0][0];
    for (size_t i = t; i < (size_t)NMAXI * 256; i += stride) h[i] = 0u;
    if (t < NMAXI) { d_bandCnt[t] = 0; d_done[t] = 0; }
}

// ---------------------------------------------------------------------------
// 2) scan1: full histogram (per-warp privatized) + last-block pass-0 pick
// ---------------------------------------------------------------------------
__global__ void k_scan1(const float4* __restrict__ obj4, int A4) {
    __shared__ unsigned wh[8][256];          // per-warp histograms
    __shared__ int s_last;
    int img = blockIdx.y;
    int tid = threadIdx.x;
    int wrp = tid >> 5;
    for (int i = tid; i < 8 * 256; i += 256) ((unsigned*)wh)[i] = 0u;
    __syncthreads();

    const float4* base = obj4 + (size_t)img * A4;
    int stride = gridDim.x * blockDim.x;
    for (int i = blockIdx.x * blockDim.x + tid; i < A4; i += stride) {
        float4 v = base[i];
        atomicAdd(&wh[wrp][key_of(v.x) >> 24], 1u);
        atomicAdd(&wh[wrp][key_of(v.y) >> 24], 1u);
        atomicAdd(&wh[wrp][key_of(v.z) >> 24], 1u);
        atomicAdd(&wh[wrp][key_of(v.w) >> 24], 1u);
    }
    __syncthreads();
    if (tid < 256) {
        unsigned s = 0;
        #pragma unroll
        for (int w = 0; w < 8; w++) s += wh[w][tid];
        if (s) atomicAdd(&d_hist[img][tid], s);
    }
    __threadfence();
    __syncthreads();
    if (tid == 0) s_last = (atomicAdd(&d_done[img], 1) == gridDim.x - 1);
    __syncthreads();
    if (!s_last) return;

    // last block of this image: pick top byte via suffix scan
    __shared__ unsigned s[256];
    if (tid < 256) s[tid] = d_hist[img][tid];
    __syncthreads();
    for (int off = 1; off < 256; off <<= 1) {
        unsigned add = 0;
        if (tid < 256 && tid + off < 256) add = s[tid + off];
        __syncthreads();
        if (tid < 256) s[tid] += add;
        __syncthreads();
    }
    if (tid < 256) {
        unsigned R = PRE;
        unsigned Sv = s[tid];
        unsigned Sn = (tid < 255) ? s[tid + 1] : 0u;
        if (Sv >= R && (tid == 255 || Sn < R)) {
            d_rankr[img]  = (int)(R - Sn);
            d_prefix[img] = ((unsigned)tid) << 24;
        }
    }
}

// ---------------------------------------------------------------------------
// 3) scan2: band compaction (keys with top byte >= picked byte)
// ---------------------------------------------------------------------------
__global__ void k_scan2(const float4* __restrict__ obj4, int A4) {
    int img = blockIdx.y;
    int tid = threadIdx.x;
    int lane = tid & 31;
    unsigned thr = d_prefix[img];            // low 24 bits are zero
    const float4* base = obj4 + (size_t)img * A4;
    int stride = gridDim.x * blockDim.x;
    int itmax = (A4 + stride - 1) / stride;
    for (int it = 0; it < itmax; it++) {
        int i = blockIdx.x * blockDim.x + tid + it * stride;
        unsigned k0 = 0, k1 = 0, k2 = 0, k3 = 0;
        if (i < A4) {
            float4 v = base[i];
            k0 = key_of(v.x); k1 = key_of(v.y); k2 = key_of(v.z); k3 = key_of(v.w);
        }
        int c = (k0 >= thr) + (k1 >= thr) + (k2 >= thr) + (k3 >= thr);
        if (i >= A4) c = 0;
        // warp-aggregated reservation
        int incl = c;
        #pragma unroll
        for (int o = 1; o < 32; o <<= 1) {
            int v = __shfl_up_sync(0xffffffffu, incl, o);
            if (lane >= o) incl += v;
        }
        int total = __shfl_sync(0xffffffffu, incl, 31);
        int basep = 0;
        if (lane == 31 && total) basep = atomicAdd(&d_bandCnt[img], total);
        basep = __shfl_sync(0xffffffffu, basep, 31);
        int pos = basep + incl - c;
        if (c) {
            unsigned bi = (unsigned)i * 4u;
            if (k0 >= thr) { if (pos < BANDCAP) d_band[img][pos] = ((unsigned long long)k0 << 32) | (unsigned)~(bi + 0); pos++; }
            if (k1 >= thr) { if (pos < BANDCAP) d_band[img][pos] = ((unsigned long long)k1 << 32) | (unsigned)~(bi + 1); pos++; }
            if (k2 >= thr) { if (pos < BANDCAP) d_band[img][pos] = ((unsigned long long)k2 << 32) | (unsigned)~(bi + 2); pos++; }
            if (k3 >= thr) { if (pos < BANDCAP) d_band[img][pos] = ((unsigned long long)k3 << 32) | (unsigned)~(bi + 3); pos++; }
        }
    }
}

// ---------------------------------------------------------------------------
// 4) mega: per-image pipeline, one 1024-thread block per image
// ---------------------------------------------------------------------------
struct SM {
    float4             box[CAP];        // 32 KB
    unsigned long long sortbuf[CAP];    // 16 KB
    float              area[CAP];       //  8 KB
    float              score[CAP];      //  8 KB
    int                tie[TIECAP];     //  4 KB
    unsigned           hist[256];       //  1 KB
    unsigned char      valid[CAP];      //  2 KB
    unsigned long long rowAny[WORDS];
    unsigned long long keep[WORDS];
    int                pref[WORDS + 1];
    unsigned           s_pref;
    int                s_rank, cntG, cntE;
};

__device__ __forceinline__ void bitonic_desc(unsigned long long* sh, int tid) {
    for (unsigned k = 2; k <= CAP; k <<= 1) {
        for (unsigned j = k >> 1; j > 0; j >>= 1) {
            for (unsigned idx = tid; idx < CAP; idx += 1024) {
                unsigned ixj = idx ^ j;
                if (ixj > idx) {
                    bool up = ((idx & k) == 0);
                    unsigned long long a = sh[idx], b = sh[ixj];
                    bool sw = up ? (a < b) : (a > b);
                    if (sw) { sh[idx] = b; sh[ixj] = a; }
                }
            }
            __syncthreads();
        }
    }
}

__global__ void k_mega(const float* __restrict__ deltas,
                       const float* __restrict__ anchors,
                       float* __restrict__ out, int A) {
    extern __shared__ char smraw[];
    SM* sm = (SM*)smraw;
    int img = blockIdx.x;
    int tid = threadIdx.x;

    if (tid == 0) {
        sm->s_pref = d_prefix[img];
        sm->s_rank = d_rankr[img];
        sm->cntG = 0; sm->cntE = 0;
    }
    if (tid < WORDS) { sm->rowAny[tid] = 0ull; sm->keep[tid] = 0ull; }
    __syncthreads();

    int n = d_bandCnt[img]; if (n > BANDCAP) n = BANDCAP;

    // --- radix passes 1..3 on band ---
    for (int pass = 1; pass < 4; pass++) {
        if (tid < 256) sm->hist[tid] = 0u;
        __syncthreads();
        unsigned pref = sm->s_pref;
        int shift = 24 - 8 * pass;
        for (int i = tid; i < n; i += 1024) {
            unsigned u = (unsigned)(d_band[img][i] >> 32);
            if (((u ^ pref) >> (shift + 8)) == 0u)
                atomicAdd(&sm->hist[(u >> shift) & 255u], 1u);
        }
        __syncthreads();
        unsigned R = (unsigned)sm->s_rank;
        for (int off = 1; off < 256; off <<= 1) {
            unsigned add = 0;
            if (tid < 256 && tid + off < 256) add = sm->hist[tid + off];
            __syncthreads();
            if (tid < 256) sm->hist[tid] += add;
            __syncthreads();
        }
        if (tid < 256) {
            unsigned Sv = sm->hist[tid];
            unsigned Sn = (tid < 255) ? sm->hist[tid + 1] : 0u;
            if (Sv >= R && (tid == 255 || Sn < R)) {
                sm->s_rank = (int)(R - Sn);
                sm->s_pref = pref | (((unsigned)tid) << shift);
            }
        }
        __syncthreads();
    }

    // --- compact: > T into sortbuf, == T indices into tie ---
    unsigned T = sm->s_pref;
    for (int i = tid; i < n; i += 1024) {
        unsigned long long pk = d_band[img][i];
        unsigned u = (unsigned)(pk >> 32);
        if (u > T) {
            int pos = atomicAdd(&sm->cntG, 1);
            if (pos < CAP) sm->sortbuf[pos] = pk;
        } else if (u == T) {
            int pos = atomicAdd(&sm->cntE, 1);
            if (pos < TIECAP) sm->tie[pos] = (int)~(unsigned)pk;
        }
    }
    __syncthreads();
    int cg = sm->cntG; if (cg > PRE) cg = PRE;
    for (int i = cg + tid; i < CAP; i += 1024) sm->sortbuf[i] = 0ull;
    __syncthreads();
    if (tid == 0) {
        int ce = sm->cntE; if (ce > TIECAP) ce = TIECAP;
        int need = PRE - cg; if (need < 0) need = 0; if (need > ce) need = ce;
        unsigned long long T64 = (unsigned long long)T << 32;
        for (int r = 0; r < need; r++) {
            int best = -1, bi = 0;
            for (int t = 0; t < ce; t++) {
                int v = sm->tie[t];
                if (v >= 0 && (best < 0 || v < best)) { best = v; bi = t; }
            }
            sm->tie[bi] = -1;
            sm->sortbuf[cg + r] = T64 | (unsigned)~(unsigned)best;
        }
    }
    __syncthreads();

    // --- sort by score key desc (tie: index asc) ---
    bitonic_desc(sm->sortbuf, tid);

    // --- decode top-2000, then reuse sortbuf as area-sort keys ---
    for (int s = tid; s < CAP; s += 1024) {
        if (s >= PRE) {
            sm->area[s] = -1.0f;
            sm->sortbuf[s] = ((unsigned long long)key_of(-1.0f) << 32) | (unsigned)s;
            continue;
        }
        unsigned long long pk = sm->sortbuf[s];
        unsigned idx = ~(unsigned)(pk & 0xffffffffull);
        unsigned kk  = (unsigned)(pk >> 32);
        unsigned ub  = (kk & 0x80000000u) ? (kk ^ 0x80000000u) : ~kk;
        float logit = __uint_as_float(ub);
        float scr = 1.0f / (1.0f + expf(-logit));

        float4 a  = *(const float4*)(anchors + (size_t)idx * 4);
        float4 dl = *(const float4*)(deltas + ((size_t)img * A + idx) * 4);

        float wa  = __fsub_rn(a.z, a.x);
        float ha  = __fsub_rn(a.w, a.y);
        float cxa = __fadd_rn(a.x, __fmul_rn(0.5f, wa));
        float cya = __fadd_rn(a.y, __fmul_rn(0.5f, ha));
        float dw  = fminf(dl.z, BBOXCLIP);
        float dh  = fminf(dl.w, BBOXCLIP);
        float pcx = __fadd_rn(__fmul_rn(dl.x, wa), cxa);
        float pcy = __fadd_rn(__fmul_rn(dl.y, ha), cya);
        float pw  = __fmul_rn(expf(dw), wa);
        float ph  = __fmul_rn(expf(dh), ha);
        float x1 = __fsub_rn(pcx, __fmul_rn(0.5f, pw));
        float y1 = __fsub_rn(pcy, __fmul_rn(0.5f, ph));
        float x2 = __fadd_rn(pcx, __fmul_rn(0.5f, pw));
        float y2 = __fadd_rn(pcy, __fmul_rn(0.5f, ph));
        x1 = fminf(fmaxf(x1, 0.0f), IMGSZ);
        y1 = fminf(fmaxf(y1, 0.0f), IMGSZ);
        x2 = fminf(fmaxf(x2, 0.0f), IMGSZ);
        y2 = fminf(fmaxf(y2, 0.0f), IMGSZ);
        float w = __fsub_rn(x2, x1);
        float h = __fsub_rn(y2, y1);
        float ar = __fmul_rn(w, h);

        sm->box[s] = make_float4(x1, y1, x2, y2);
        sm->area[s] = ar;
        sm->score[s] = scr;
        sm->valid[s] = (w >= MINSZ) && (h >= MINSZ) && (scr > 0.0f);
        sm->sortbuf[s] = ((unsigned long long)key_of(ar) << 32) | (unsigned)s;
    }
    __syncthreads();

    // --- sort by area desc ---
    bitonic_desc(sm->sortbuf, tid);

    // --- windowed exact IoU pairs (IoU <= min/max area screen) ---
    {
        int wid = tid >> 5, lane = tid & 31;
        for (int p = wid; p < CAP - 1; p += 32) {
            int sp = (int)(unsigned)(sm->sortbuf[p] & 0xffffffffull);
            float ap = sm->area[sp];
            if (ap < 0.0f) continue;
            float thr = 0.69f * ap;
            float4 bp = sm->box[sp];
            for (int qb = p + 1; qb < CAP; qb += 32) {
                int q = qb + lane;
                bool act = false; int sq = 0; float aq = 0.0f;
                if (q < CAP) {
                    sq = (int)(unsigned)(sm->sortbuf[q] & 0xffffffffull);
                    aq = sm->area[sq];
                    act = (aq >= thr);
                }
                if (act) {
                    float4 bq = sm->box[sq];
                    float xx1 = fmaxf(bp.x, bq.x);
                    float yy1 = fmaxf(bp.y, bq.y);
                    float xx2 = fminf(bp.z, bq.z);
                    float yy2 = fminf(bp.w, bq.w);
                    float iw = fmaxf(__fsub_rn(xx2, xx1), 0.0f);
                    float ih = fmaxf(__fsub_rn(yy2, yy1), 0.0f);
                    float inter = __fmul_rn(iw, ih);
                    float den = __fadd_rn(__fsub_rn(__fadd_rn(ap, aq), inter), 1e-12f);
                    float iou = __fdiv_rn(inter, den);
                    if (iou > IOUTHR) {
                        int i = sp < sq ? sp : sq;
                        int j = sp < sq ? sq : sp;
                        atomicOr(&d_mask[img][i][j >> 6], 1ull << (j & 63));
                        atomicOr(&sm->rowAny[i >> 6], 1ull << (i & 63));
                    }
                }
                if (__ballot_sync(0xffffffffu, act) != 0xffffffffu) break;
            }
        }
    }
    __syncthreads();

    // --- sparse greedy NMS resolve (warp 0) ---
    if (tid < 32) {
        int lane = tid;
        unsigned long long validw = 0ull;
        for (int k = 0; k < 64; k++) {
            int i = lane * 64 + k;
            if (i < PRE && sm->valid[i]) validw |= 1ull << k;
        }
        unsigned long long remv = 0ull, keepw = 0ull;
        unsigned long long rowAny_l = sm->rowAny[lane];
        unsigned long long dg0 = d_mask[img][lane][0];
        unsigned long long dg1 = d_mask[img][32 + lane][0];
        for (int c = 0; c < 32; c++) {
            unsigned long long ndg0 = 0ull, ndg1 = 0ull;
            if (c < 31) {
                ndg0 = d_mask[img][(c + 1) * 64 + lane][c + 1];
                ndg1 = d_mask[img][(c + 1) * 64 + 32 + lane][c + 1];
            }
            unsigned long long vw = __shfl_sync(0xffffffffu, validw, c);
            unsigned long long rm = __shfl_sync(0xffffffffu, remv, c);
            unsigned b0 = __ballot_sync(0xffffffffu, dg0 != 0ull);
            unsigned b1 = __ballot_sync(0xffffffffu, dg1 != 0ull);
            unsigned long long D = (unsigned long long)b0 | ((unsigned long long)b1 << 32);
            unsigned long long keep = 0ull;
            int pos = 0;
            unsigned long long Dw = D;
            while (Dw) {
                int r = __ffsll((long long)Dw) - 1; Dw &= Dw - 1;
                unsigned long long rangeM = ((1ull << (r - pos)) - 1ull) << pos;
                keep |= vw & ~rm & rangeM;
                unsigned long long dr = (r < 32) ? __shfl_sync(0xffffffffu, dg0, r)
                                                 : __shfl_sync(0xffffffffu, dg1, r - 32);
                if (((vw >> r) & 1ull) && !((rm >> r) & 1ull)) { keep |= 1ull << r; rm |= dr; }
                pos = r + 1;
            }
            if (pos < 64) keep |= vw & ~rm & ((~0ull) << pos);
            if (lane == c) keepw = keep;
            unsigned long long rAc = __shfl_sync(0xffffffffu, rowAny_l, c);
            unsigned long long todo = keep & rAc;
            while (todo) {
                int r = __ffsll((long long)todo) - 1; todo &= todo - 1;
                remv |= d_mask[img][c * 64 + r][lane];
            }
            dg0 = ndg0; dg1 = ndg1;
        }
        sm->keep[lane] = keepw;
    }
    __syncthreads();

    // --- stable partition output ---
    if (tid == 0) {
        int acc = 0;
        for (int w = 0; w < WORDS; w++) { sm->pref[w] = acc; acc += __popcll(sm->keep[w]); }
        sm->pref[WORDS] = acc;
    }
    __syncthreads();
    int cnt = sm->pref[WORDS];
    for (int p = tid; p < PRE; p += 1024) {
        int w = p >> 6, b = p & 63;
        unsigned long long word = sm->keep[w];
        int before = sm->pref[w] + __popcll(word & ((b == 0) ? 0ull : ((~0ull) >> (64 - b))));
        bool kp = (word >> b) & 1ull;
        int slot = kp ? before : (cnt + (p - before));
        if (slot < POST) {
            float4 bx = sm->box[p];
            float* o = out + ((size_t)img * POST + slot) * 5;
            o[0] = bx.x; o[1] = bx.y; o[2] = bx.z; o[3] = bx.w;
            o[4] = kp ? sm->score[p] : 0.0f;
        }
    }
}

// ------------------------------- launch ------------------------------------
extern "C" void kernel_launch(void* const* d_in, const int* in_sizes, int n_in,
                              void* d_out, int out_size) {
    const float* obj     = (const float*)d_in[0];
    const float* deltas  = (const float*)d_in[1];
    const float* anchors = (const float*)d_in[2];
    float* out = (float*)d_out;

    int A = in_sizes[2] / 4;
    int N = in_sizes[0] / A;
    if (N > NMAXI) N = NMAXI;
    int A4 = A / 4;

    cudaFuncSetAttribute(k_mega, cudaFuncAttributeMaxDynamicSharedMemorySize,
                         (int)sizeof(SM));

    k_prep<<<512, 256>>>();
    k_scan1<<<dim3(SCANB, N), 256>>>((const float4*)obj, A4);
    k_scan2<<<dim3(SCANB, N), 256>>>((const float4*)obj, A4);
    k_mega<<<N, 1024, sizeof(SM)>>>(deltas, anchors, out, A);
}